// round 2
// baseline (speedup 1.0000x reference)
#include <cuda_runtime.h>
#include <cstdint>

#define T_ 256
#define B_ 64
#define M_ 512
#define N_ 1024
#define NB_REC 128

// Scratch: G[dir*3+gate][t][n][b]  (gate order f,i,c)
__device__ float g_G[(size_t)6 * T_ * N_ * B_];
// h double buffer: [buf][dir][n*64+b]
__device__ float g_h[2][2][N_ * B_];
// per-step grid barrier counters (zeroed by k_init every launch)
__device__ unsigned g_bar[T_];

struct PW { const float* p[6]; };
struct PU { const float* U[8]; const float* bia[8]; };

__device__ __forceinline__ uint32_t f2tf(float v) {
  uint32_t u; asm("cvt.rna.tf32.f32 %0, %1;" : "=r"(u) : "f"(v)); return u;
}
__device__ __forceinline__ void mma8(float* c, uint32_t a0, uint32_t a1,
                                     uint32_t a2, uint32_t a3,
                                     uint32_t b0, uint32_t b1) {
  asm volatile(
    "mma.sync.aligned.m16n8k8.row.col.f32.tf32.tf32.f32 "
    "{%0,%1,%2,%3},{%4,%5,%6,%7},{%8,%9},{%0,%1,%2,%3};\n"
    : "+f"(c[0]), "+f"(c[1]), "+f"(c[2]), "+f"(c[3])
    : "r"(a0), "r"(a1), "r"(a2), "r"(a3), "r"(b0), "r"(b1));
}

__global__ void k_init(const float* __restrict__ hidden) {
  int i = blockIdx.x * blockDim.x + threadIdx.x;
  if (i < N_ * B_) {
    int n = i >> 6, b = i & 63;
    float v = hidden[b * N_ + n];   // h0 = hidden^T
    g_h[0][0][i] = v;
    g_h[0][1][i] = v;
  }
  if (i < T_) g_bar[i] = 0;
}

// ---------------- Phase 1: G[dg][t][n][b] = sum_m x[t_src,b,m] * W[m,n] ----
__global__ void __launch_bounds__(256) k_gemm_xw(const float* __restrict__ x, PW pw) {
  __shared__ __align__(16) float As[64][36];    // pad 36: conflict-free A frags
  __shared__ __align__(16) float Bs[32][136];   // pad 136 (=8 mod 32): conflict-free B frags
  int tid = threadIdx.x;
  int wid = tid >> 5, lane = tid & 31;
  int g4 = lane >> 2, tq = lane & 3;
  int wm = wid & 1, wn = wid >> 1;            // warp grid 2 x 4 over 64 x 128 tile
  int n0 = blockIdx.x * 128;
  int t = blockIdx.y;
  int dg = blockIdx.z;                         // dir*3 + gate
  int dir = dg / 3;
  int t_src = dir ? (T_ - 1 - t) : t;
  const float* W = pw.p[dg];
  const float* xt = x + (size_t)t_src * (B_ * M_);

  float acc[2][4][4];
  #pragma unroll
  for (int a = 0; a < 2; a++)
    #pragma unroll
    for (int b = 0; b < 4; b++)
      #pragma unroll
      for (int cc = 0; cc < 4; cc++) acc[a][b][cc] = 0.f;

  for (int k0 = 0; k0 < M_; k0 += 32) {
    #pragma unroll
    for (int j = 0; j < 2; j++) {            // A tile: 64x32
      int i = tid + j * 256;
      int bb = i >> 3, kq = (i & 7) << 2;
      *(float4*)&As[bb][kq] = *(const float4*)(xt + bb * M_ + k0 + kq);
    }
    #pragma unroll
    for (int j = 0; j < 4; j++) {            // B tile: 32x128
      int i = tid + j * 256;
      int kk = i >> 5, nq = (i & 31) << 2;
      *(float4*)&Bs[kk][nq] = *(const float4*)(W + (size_t)(k0 + kk) * N_ + n0 + nq);
    }
    __syncthreads();
    #pragma unroll
    for (int ks = 0; ks < 32; ks += 8) {
      uint32_t af[2][4];
      #pragma unroll
      for (int mt = 0; mt < 2; mt++) {
        int r = wm * 32 + mt * 16 + g4;
        af[mt][0] = f2tf(As[r][ks + tq]);
        af[mt][1] = f2tf(As[r + 8][ks + tq]);
        af[mt][2] = f2tf(As[r][ks + tq + 4]);
        af[mt][3] = f2tf(As[r + 8][ks + tq + 4]);
      }
      #pragma unroll
      for (int nt = 0; nt < 4; nt++) {
        int ccol = wn * 32 + nt * 8 + g4;
        uint32_t b0 = f2tf(Bs[ks + tq][ccol]);
        uint32_t b1 = f2tf(Bs[ks + tq + 4][ccol]);
        #pragma unroll
        for (int mt = 0; mt < 2; mt++)
          mma8(acc[mt][nt], af[mt][0], af[mt][1], af[mt][2], af[mt][3], b0, b1);
      }
    }
    __syncthreads();
  }
  // store: C row = b (batch), C col = n.  G[dg][t][n][b]
  size_t gb = (size_t)(dg * T_ + t) * (N_ * B_);
  #pragma unroll
  for (int mt = 0; mt < 2; mt++) {
    int brow = wm * 32 + mt * 16 + g4;
    #pragma unroll
    for (int nt = 0; nt < 4; nt++) {
      int nc = n0 + wn * 32 + nt * 8 + 2 * tq;
      g_G[gb + (size_t)nc * B_ + brow]           = acc[mt][nt][0];
      g_G[gb + (size_t)(nc + 1) * B_ + brow]     = acc[mt][nt][1];
      g_G[gb + (size_t)nc * B_ + brow + 8]       = acc[mt][nt][2];
      g_G[gb + (size_t)(nc + 1) * B_ + brow + 8] = acc[mt][nt][3];
    }
  }
}

// ---------------- Phase 2: persistent recurrent kernel ---------------------
// gate index: 0=f, 1=i, 2=c~, 3=o   (o reuses gf per the reference's bug)
__global__ void __launch_bounds__(256) k_recur(PU pu, float* __restrict__ out) {
  __shared__ __align__(16) float hs[64][72];   // pad 72 (=8 mod 32): conflict-free B frags
  __shared__ __align__(16) float zs[4][16][64];
  int tid = threadIdx.x;
  int wid = tid >> 5, lane = tid & 31;
  int g4 = lane >> 2, tq = lane & 3;
  int dir = blockIdx.x >> 6;
  int rn = (blockIdx.x & 63) << 4;             // 16 n-rows per block
  int gate = wid >> 1, half = wid & 1;         // 2 warps per gate (32 b-cols each)

  const float* U = pu.U[dir * 4 + gate];
  int gsel = (gate == 3) ? 0 : gate;
  const float* Gg = g_G + (size_t)(dir * 3 + gsel) * T_ * N_ * B_;
  float bias0 = pu.bia[dir * 4 + gate][rn + g4];
  float bias1 = pu.bia[dir * 4 + gate][rn + g4 + 8];
  const float* Ur0 = U + (size_t)(rn + g4) * N_;
  const float* Ur1 = U + (size_t)(rn + g4 + 8) * N_;

  int erow = tid >> 4;                         // elementwise: e = tid*4..tid*4+3
  int ecol = (tid & 15) << 2;
  float creg[4] = {0.f, 0.f, 0.f, 0.f};        // cell state, lives in registers

  for (int s = 0; s < T_; ++s) {
    const float* hsrc = g_h[s & 1][dir];
    float acc[4][4];
    #pragma unroll
    for (int a = 0; a < 4; a++)
      #pragma unroll
      for (int b = 0; b < 4; b++) acc[a][b] = 0.f;

    for (int c0 = 0; c0 < N_; c0 += 64) {
      #pragma unroll
      for (int j = 0; j < 4; j++) {            // stage h chunk 64x64 (L2, bypass L1)
        int i = tid + j * 256;
        int kk = i >> 4, b4 = (i & 15) << 2;
        float4 v = __ldcg((const float4*)(hsrc + (c0 + kk) * 64 + b4));
        *(float4*)&hs[kk][b4] = v;
      }
      __syncthreads();
      #pragma unroll
      for (int ks = 0; ks < 64; ks += 8) {
        int k = c0 + ks;
        uint32_t a0 = f2tf(__ldg(Ur0 + k + tq));
        uint32_t a1 = f2tf(__ldg(Ur1 + k + tq));
        uint32_t a2 = f2tf(__ldg(Ur0 + k + tq + 4));
        uint32_t a3 = f2tf(__ldg(Ur1 + k + tq + 4));
        #pragma unroll
        for (int nt = 0; nt < 4; nt++) {
          int col = half * 32 + nt * 8 + g4;
          uint32_t b0 = f2tf(hs[ks + tq][col]);
          uint32_t b1 = f2tf(hs[ks + tq + 4][col]);
          mma8(acc[nt], a0, a1, a2, a3, b0, b1);
        }
      }
      __syncthreads();
    }

    // epilogue: z = U@h + G + bias  -> smem for cross-warp gate exchange
    const float* Gt = Gg + (size_t)s * (N_ * B_) + (size_t)rn * B_;
    #pragma unroll
    for (int nt = 0; nt < 4; nt++) {
      int col = half * 32 + nt * 8 + 2 * tq;
      zs[gate][g4][col]         = acc[nt][0] + Gt[g4 * 64 + col] + bias0;
      zs[gate][g4][col + 1]     = acc[nt][1] + Gt[g4 * 64 + col + 1] + bias0;
      zs[gate][g4 + 8][col]     = acc[nt][2] + Gt[(g4 + 8) * 64 + col] + bias1;
      zs[gate][g4 + 8][col + 1] = acc[nt][3] + Gt[(g4 + 8) * 64 + col + 1] + bias1;
    }
    __syncthreads();

    float4 hv;
    #pragma unroll
    for (int j = 0; j < 4; j++) {
      float zf = zs[0][erow][ecol + j];
      float zi = zs[1][erow][ecol + j];
      float zc = zs[2][erow][ecol + j];
      float zo = zs[3][erow][ecol + j];
      float f  = 1.f / (1.f + __expf(-zf));
      float ig = 1.f / (1.f + __expf(-zi));
      float o  = 1.f / (1.f + __expf(-zo));
      float cn = f * creg[j] + ig * tanhf(zc);
      creg[j] = cn;
      ((float*)&hv)[j] = o * tanhf(cn);
    }
    float* hdst = g_h[(s + 1) & 1][dir];
    __stcg((float4*)(hdst + (rn + erow) * 64 + ecol), hv);

    int t_out = dir ? (T_ - 1 - s) : s;
    size_t ob = ((size_t)t_out * B_ + ecol) * (2 * N_) + (size_t)dir * N_ + rn + erow;
    out[ob]              = hv.x;
    out[ob + 2 * N_]     = hv.y;
    out[ob + 4 * N_]     = hv.z;
    out[ob + 6 * N_]     = hv.w;

    // grid barrier (per-step counter, no reset race, replay-safe)
    if (s < T_ - 1) {
      __threadfence();
      __syncthreads();
      if (tid == 0) {
        unsigned v = atomicAdd(&g_bar[s], 1) + 1;
        if (v < NB_REC) {
          while (*(volatile unsigned*)&g_bar[s] < NB_REC) { __nanosleep(64); }
        }
      }
      __syncthreads();
    }
  }
}

extern "C" void kernel_launch(void* const* d_in, const int* in_sizes, int n_in,
                              void* d_out, int out_size) {
  const float* x      = (const float*)d_in[0];
  const float* hidden = (const float*)d_in[1];
  // inputs: x,hidden, Wf1,Wi1,Wc1, Uf1,Ui1,Uo1,Uc1, bf1,bi1,bo1,bc1,
  //                   Wf2,Wi2,Wc2, Uf2,Ui2,Uo2,Uc2, bf2,bi2,bo2,bc2
  PW pw;
  pw.p[0] = (const float*)d_in[2];   // Wf1
  pw.p[1] = (const float*)d_in[3];   // Wi1
  pw.p[2] = (const float*)d_in[4];   // Wc1
  pw.p[3] = (const float*)d_in[13];  // Wf2
  pw.p[4] = (const float*)d_in[14];  // Wi2
  pw.p[5] = (const float*)d_in[15];  // Wc2

  PU pu;
  // gate order f,i,c,o
  pu.U[0] = (const float*)d_in[5];   // Uf1
  pu.U[1] = (const float*)d_in[6];   // Ui1
  pu.U[2] = (const float*)d_in[8];   // Uc1
  pu.U[3] = (const float*)d_in[7];   // Uo1
  pu.U[4] = (const float*)d_in[16];  // Uf2
  pu.U[5] = (const float*)d_in[17];  // Ui2
  pu.U[6] = (const float*)d_in[19];  // Uc2
  pu.U[7] = (const float*)d_in[18];  // Uo2
  pu.bia[0] = (const float*)d_in[9];   // bf1
  pu.bia[1] = (const float*)d_in[10];  // bi1
  pu.bia[2] = (const float*)d_in[12];  // bc1
  pu.bia[3] = (const float*)d_in[11];  // bo1
  pu.bia[4] = (const float*)d_in[20];  // bf2
  pu.bia[5] = (const float*)d_in[21];  // bi2
  pu.bia[6] = (const float*)d_in[23];  // bc2
  pu.bia[7] = (const float*)d_in[22];  // bo2

  k_init<<<256, 256>>>(hidden);
  k_gemm_xw<<<dim3(8, 256, 6), 256>>>(x, pw);
  k_recur<<<NB_REC, 256>>>(pu, (float*)d_out);
}

// round 3
// speedup vs baseline: 1.7870x; 1.7870x over previous
#include <cuda_runtime.h>
#include <cstdint>

#define T_ 256
#define B_ 64
#define M_ 512
#define N_ 1024
#define NB_REC 128

// Scratch: G[dir*3+gate][t][n][b]  (gate order f,i,c)
__device__ float g_G[(size_t)6 * T_ * N_ * B_];
// h double buffer, transposed + tf32-rounded: [buf][dir][b*N + k]
__device__ float g_hT[2][2][B_ * N_];
// U packed in mma-fragment order as tf32 bit patterns:
// [dir][ntile 64][kq 4][ksj 32][gate 4][lane 32] uint4 = (a0,a1,a2,a3)
__device__ uint4 g_Upk[1u << 21];
// per-step grid barrier counters (zeroed by k_init every launch)
__device__ unsigned g_bar[T_];

struct PW { const float* p[6]; };
struct PU { const float* U[8]; const float* bia[8]; };

__device__ __forceinline__ uint32_t f2tf(float v) {
  uint32_t u; asm("cvt.rna.tf32.f32 %0, %1;" : "=r"(u) : "f"(v)); return u;
}
__device__ __forceinline__ void mma8(float* c, uint32_t a0, uint32_t a1,
                                     uint32_t a2, uint32_t a3,
                                     uint32_t b0, uint32_t b1) {
  asm volatile(
    "mma.sync.aligned.m16n8k8.row.col.f32.tf32.tf32.f32 "
    "{%0,%1,%2,%3},{%4,%5,%6,%7},{%8,%9},{%0,%1,%2,%3};\n"
    : "+f"(c[0]), "+f"(c[1]), "+f"(c[2]), "+f"(c[3])
    : "r"(a0), "r"(a1), "r"(a2), "r"(a3), "r"(b0), "r"(b1));
}

__global__ void k_init(const float* __restrict__ hidden) {
  int i = blockIdx.x * blockDim.x + threadIdx.x;
  if (i < B_ * N_) {
    float v = __uint_as_float(f2tf(hidden[i]));   // hT[b][n] = round(hidden[b][n])
    g_hT[0][0][i] = v;
    g_hT[0][1][i] = v;
  }
  if (i < T_) g_bar[i] = 0;
}

// Pack U into fragment order (one uint4 per thread).
__global__ void __launch_bounds__(256) k_pack(PU pu) {
  unsigned i = blockIdx.x * 256 + threadIdx.x;
  unsigned lane = i & 31, gate = (i >> 5) & 3, ksj = (i >> 7) & 31,
           kq = (i >> 12) & 3, ntile = (i >> 14) & 63, dir = (i >> 20) & 1;
  int g4 = lane >> 2, tq = lane & 3;
  int row = ntile * 16 + g4;
  int k = kq * 256 + ksj * 8 + tq;
  const float* U = pu.U[dir * 4 + gate];
  uint4 o;
  o.x = f2tf(U[(size_t)row * N_ + k]);
  o.y = f2tf(U[(size_t)(row + 8) * N_ + k]);
  o.z = f2tf(U[(size_t)row * N_ + k + 4]);
  o.w = f2tf(U[(size_t)(row + 8) * N_ + k + 4]);
  g_Upk[i] = o;
}

// ---------------- Phase 1: G[dg][t][n][b] = sum_m x[t_src,b,m] * W[m,n] ----
__device__ __forceinline__ float4 cvt4(float4 v) {
  float4 r;
  r.x = __uint_as_float(f2tf(v.x)); r.y = __uint_as_float(f2tf(v.y));
  r.z = __uint_as_float(f2tf(v.z)); r.w = __uint_as_float(f2tf(v.w));
  return r;
}

__global__ void __launch_bounds__(256) k_gemm_xw(const float* __restrict__ x, PW pw) {
  __shared__ __align__(16) float As[64][36];
  __shared__ __align__(16) float Bs[32][136];
  int tid = threadIdx.x;
  int wid = tid >> 5, lane = tid & 31;
  int g4 = lane >> 2, tq = lane & 3;
  int wm = wid & 1, wn = wid >> 1;
  int n0 = blockIdx.x * 128;
  int t = blockIdx.y;
  int dg = blockIdx.z;
  int dir = dg / 3;
  int t_src = dir ? (T_ - 1 - t) : t;
  const float* W = pw.p[dg];
  const float* xt = x + (size_t)t_src * (B_ * M_);

  float acc[2][4][4];
  #pragma unroll
  for (int a = 0; a < 2; a++)
    #pragma unroll
    for (int b = 0; b < 4; b++)
      #pragma unroll
      for (int cc = 0; cc < 4; cc++) acc[a][b][cc] = 0.f;

  for (int k0 = 0; k0 < M_; k0 += 32) {
    #pragma unroll
    for (int j = 0; j < 2; j++) {
      int i = tid + j * 256;
      int bb = i >> 3, kq = (i & 7) << 2;
      *(float4*)&As[bb][kq] = cvt4(*(const float4*)(xt + bb * M_ + k0 + kq));
    }
    #pragma unroll
    for (int j = 0; j < 4; j++) {
      int i = tid + j * 256;
      int kk = i >> 5, nq = (i & 31) << 2;
      *(float4*)&Bs[kk][nq] = cvt4(*(const float4*)(W + (size_t)(k0 + kk) * N_ + n0 + nq));
    }
    __syncthreads();
    #pragma unroll
    for (int ks = 0; ks < 32; ks += 8) {
      uint32_t af[2][4];
      #pragma unroll
      for (int mt = 0; mt < 2; mt++) {
        int r = wm * 32 + mt * 16 + g4;
        af[mt][0] = __float_as_uint(As[r][ks + tq]);
        af[mt][1] = __float_as_uint(As[r + 8][ks + tq]);
        af[mt][2] = __float_as_uint(As[r][ks + tq + 4]);
        af[mt][3] = __float_as_uint(As[r + 8][ks + tq + 4]);
      }
      #pragma unroll
      for (int nt = 0; nt < 4; nt++) {
        int ccol = wn * 32 + nt * 8 + g4;
        uint32_t b0 = __float_as_uint(Bs[ks + tq][ccol]);
        uint32_t b1 = __float_as_uint(Bs[ks + tq + 4][ccol]);
        #pragma unroll
        for (int mt = 0; mt < 2; mt++)
          mma8(acc[mt][nt], af[mt][0], af[mt][1], af[mt][2], af[mt][3], b0, b1);
      }
    }
    __syncthreads();
  }
  size_t gb = (size_t)(dg * T_ + t) * (N_ * B_);
  #pragma unroll
  for (int mt = 0; mt < 2; mt++) {
    int brow = wm * 32 + mt * 16 + g4;
    #pragma unroll
    for (int nt = 0; nt < 4; nt++) {
      int nc = n0 + wn * 32 + nt * 8 + 2 * tq;
      g_G[gb + (size_t)nc * B_ + brow]           = acc[mt][nt][0];
      g_G[gb + (size_t)(nc + 1) * B_ + brow]     = acc[mt][nt][1];
      g_G[gb + (size_t)nc * B_ + brow + 8]       = acc[mt][nt][2];
      g_G[gb + (size_t)(nc + 1) * B_ + brow + 8] = acc[mt][nt][3];
    }
  }
}

// ---------------- Phase 2: persistent recurrent kernel ---------------------
// warp = (kq = k-quarter, ch = b-col half): 64 rows (4 gates x 16) x 32 cols x 256 k
// smem: bs[4][64 cols][72 slots] staging (k-permuted for LDS.64 B-frags)
//       zs[(kq*4+gate)*16 + n][72] partial sums
#define BS_IDX(q, c, s2) (((q) * 64 + (c)) * 72 + (s2))
#define ZS_OFF 18432
#define ZS_IDX(q, g, n, b) (ZS_OFF + ((((q) * 4 + (g)) * 16 + (n)) * 72 + (b)))

__global__ void __launch_bounds__(256) k_recur(PU pu, float* __restrict__ out) {
  extern __shared__ float sm[];
  int tid = threadIdx.x, wid = tid >> 5, lane = tid & 31;
  int g4 = lane >> 2, tq = lane & 3;
  int dir = blockIdx.x >> 6, ntile = blockIdx.x & 63, rn = ntile << 4;
  int kq = wid >> 1, ch = wid & 1;

  const uint4* up_base = g_Upk + ((((size_t)dir * 64 + ntile) * 4 + kq) << 12);

  // elementwise ownership: b = erow, n = rn + ecol .. +3
  int erow = tid & 63;
  int ecol = (tid >> 6) << 2;

  float bia[4][4];
  #pragma unroll
  for (int g = 0; g < 4; g++)
    #pragma unroll
    for (int i = 0; i < 4; i++) bia[g][i] = pu.bia[dir * 4 + g][rn + ecol + i];
  const float* Gb0 = g_G + (size_t)(dir * 3 + 0) * T_ * N_ * B_;
  const float* Gb1 = g_G + (size_t)(dir * 3 + 1) * T_ * N_ * B_;
  const float* Gb2 = g_G + (size_t)(dir * 3 + 2) * T_ * N_ * B_;

  float creg[4] = {0.f, 0.f, 0.f, 0.f};

  for (int s = 0; s < T_; ++s) {
    const float* hsrc = g_hT[s & 1][dir];
    float acc[4][4][4];
    #pragma unroll
    for (int g = 0; g < 4; g++)
      #pragma unroll
      for (int nt = 0; nt < 4; nt++)
        #pragma unroll
        for (int cc = 0; cc < 4; cc++) acc[g][nt][cc] = 0.f;

    for (int j = 0; j < 4; j++) {
      // stage 4 chunks (one per kq) of 64 k-rows x 64 b, transposed + k-permuted
      #pragma unroll
      for (int it = 0; it < 8; it++) {
        int gI = tid + it * 256;
        int q = gI >> 9;
        int b = (gI >> 3) & 63;
        int k8 = gI & 7;
        const float* src = hsrc + b * N_ + q * 256 + j * 64 + k8 * 8;
        float4 v0 = __ldcg((const float4*)src);
        float4 v1 = __ldcg((const float4*)(src + 4));
        float* d = &sm[BS_IDX(q, b, k8 * 8)];
        ((float2*)d)[0] = make_float2(v0.x, v1.x);
        ((float2*)d)[1] = make_float2(v0.y, v1.y);
        ((float2*)d)[2] = make_float2(v0.z, v1.z);
        ((float2*)d)[3] = make_float2(v0.w, v1.w);
      }
      __syncthreads();

      const uint4* up = up_base + (size_t)j * 8 * 4 * 32;
      #pragma unroll
      for (int ks = 0; ks < 8; ks++) {
        uint4 A0 = up[(ks * 4 + 0) * 32 + lane];
        uint4 A1 = up[(ks * 4 + 1) * 32 + lane];
        uint4 A2 = up[(ks * 4 + 2) * 32 + lane];
        uint4 A3 = up[(ks * 4 + 3) * 32 + lane];
        uint2 Bv[4];
        #pragma unroll
        for (int nt = 0; nt < 4; nt++)
          Bv[nt] = *(const uint2*)&sm[BS_IDX(kq, ch * 32 + nt * 8 + g4, ks * 8 + 2 * tq)];
        #pragma unroll
        for (int nt = 0; nt < 4; nt++) {
          mma8(acc[0][nt], A0.x, A0.y, A0.z, A0.w, Bv[nt].x, Bv[nt].y);
          mma8(acc[1][nt], A1.x, A1.y, A1.z, A1.w, Bv[nt].x, Bv[nt].y);
          mma8(acc[2][nt], A2.x, A2.y, A2.z, A2.w, Bv[nt].x, Bv[nt].y);
          mma8(acc[3][nt], A3.x, A3.y, A3.z, A3.w, Bv[nt].x, Bv[nt].y);
        }
      }
      __syncthreads();
    }

    // store k-partials for cross-warp reduction
    #pragma unroll
    for (int g = 0; g < 4; g++)
      #pragma unroll
      for (int nt = 0; nt < 4; nt++) {
        int col = ch * 32 + nt * 8 + 2 * tq;
        *(float2*)&sm[ZS_IDX(kq, g, g4, col)] =
            make_float2(acc[g][nt][0], acc[g][nt][1]);
        *(float2*)&sm[ZS_IDX(kq, g, g4 + 8, col)] =
            make_float2(acc[g][nt][2], acc[g][nt][3]);
      }
    __syncthreads();

    // elementwise LSTM cell
    size_t goff = (size_t)s * (N_ * B_) + (size_t)(rn + ecol) * B_ + erow;
    float4 hv, hvr;
    #pragma unroll
    for (int i = 0; i < 4; i++) {
      float z0 = bia[0][i], z1 = bia[1][i], z2 = bia[2][i], z3 = bia[3][i];
      #pragma unroll
      for (int q = 0; q < 4; q++) {
        z0 += sm[ZS_IDX(q, 0, ecol + i, erow)];
        z1 += sm[ZS_IDX(q, 1, ecol + i, erow)];
        z2 += sm[ZS_IDX(q, 2, ecol + i, erow)];
        z3 += sm[ZS_IDX(q, 3, ecol + i, erow)];
      }
      float gf = Gb0[goff + (size_t)i * B_];
      float gi = Gb1[goff + (size_t)i * B_];
      float gc = Gb2[goff + (size_t)i * B_];
      float zf = z0 + gf, zi = z1 + gi, zc = z2 + gc, zo = z3 + gf; // o reuses gf
      float f  = 1.f / (1.f + __expf(-zf));
      float ig = 1.f / (1.f + __expf(-zi));
      float o  = 1.f / (1.f + __expf(-zo));
      float cn = f * creg[i] + ig * tanhf(zc);
      creg[i] = cn;
      float h = o * tanhf(cn);
      ((float*)&hv)[i]  = h;
      ((float*)&hvr)[i] = __uint_as_float(f2tf(h));
    }
    float* hdst = g_hT[(s + 1) & 1][dir];
    __stcg((float4*)(hdst + erow * N_ + rn + ecol), hvr);

    int t_out = dir ? (T_ - 1 - s) : s;
    *(float4*)(out + ((size_t)t_out * B_ + erow) * (2 * N_) + (size_t)dir * N_ + rn + ecol) = hv;

    // grid barrier (per-step counter, replay-safe)
    if (s < T_ - 1) {
      __threadfence();
      __syncthreads();
      if (tid == 0) {
        unsigned v = atomicAdd(&g_bar[s], 1) + 1;
        if (v < NB_REC) {
          while (*(volatile unsigned*)&g_bar[s] < NB_REC) { __nanosleep(64); }
        }
      }
      __syncthreads();
    }
  }
}

extern "C" void kernel_launch(void* const* d_in, const int* in_sizes, int n_in,
                              void* d_out, int out_size) {
  const float* x      = (const float*)d_in[0];
  const float* hidden = (const float*)d_in[1];
  PW pw;
  pw.p[0] = (const float*)d_in[2];   // Wf1
  pw.p[1] = (const float*)d_in[3];   // Wi1
  pw.p[2] = (const float*)d_in[4];   // Wc1
  pw.p[3] = (const float*)d_in[13];  // Wf2
  pw.p[4] = (const float*)d_in[14];  // Wi2
  pw.p[5] = (const float*)d_in[15];  // Wc2

  PU pu;  // gate order f,i,c,o
  pu.U[0] = (const float*)d_in[5];   // Uf1
  pu.U[1] = (const float*)d_in[6];   // Ui1
  pu.U[2] = (const float*)d_in[8];   // Uc1
  pu.U[3] = (const float*)d_in[7];   // Uo1
  pu.U[4] = (const float*)d_in[16];  // Uf2
  pu.U[5] = (const float*)d_in[17];  // Ui2
  pu.U[6] = (const float*)d_in[19];  // Uc2
  pu.U[7] = (const float*)d_in[18];  // Uo2
  pu.bia[0] = (const float*)d_in[9];   // bf1
  pu.bia[1] = (const float*)d_in[10];  // bi1
  pu.bia[2] = (const float*)d_in[12];  // bc1
  pu.bia[3] = (const float*)d_in[11];  // bo1
  pu.bia[4] = (const float*)d_in[20];  // bf2
  pu.bia[5] = (const float*)d_in[21];  // bi2
  pu.bia[6] = (const float*)d_in[23];  // bc2
  pu.bia[7] = (const float*)d_in[22];  // bo2

  static int smem_set = 0;
  if (!smem_set) {
    cudaFuncSetAttribute(k_recur, cudaFuncAttributeMaxDynamicSharedMemorySize,
                         (18432 + 4 * 4 * 16 * 72) * sizeof(float));
    smem_set = 1;
  }

  k_init<<<256, 256>>>(hidden);
  k_pack<<<8192, 256>>>(pu);
  k_gemm_xw<<<dim3(8, 256, 6), 256>>>(x, pw);
  k_recur<<<NB_REC, 256, (18432 + 4 * 4 * 16 * 72) * sizeof(float)>>>(pu, (float*)d_out);
}

// round 5
// speedup vs baseline: 2.3099x; 1.2926x over previous
#include <cuda_runtime.h>
#include <cstdint>

#define T_ 256
#define B_ 64
#define M_ 512
#define N_ 1024
#define NB_REC 128
#define NBD 64          // blocks per direction (barrier arrivals)

// Scratch: G[dir*3+gate][t][n][b]  (gate order f,i,c)
__device__ float g_G[(size_t)6 * T_ * N_ * B_];
// h double buffer, k-pair-permuted + tf32-rounded: [buf][dir][b][kslot 1024]
__device__ float g_hP[2][2][B_ * N_];
// U packed in mma-fragment order as tf32 bit patterns:
// [dir][tile 64][chunk 4][kq 8][ks 4][gate 4][lane 32] uint4
__device__ uint4 g_Upk[1u << 21];
// per-step per-dir grid barrier counters (zeroed by k_init every launch)
__device__ unsigned g_bar[2 * T_];

struct PW { const float* p[6]; };
struct PU { const float* U[8]; const float* bia[8]; };

__device__ __forceinline__ uint32_t f2tf(float v) {
  uint32_t u; asm("cvt.rna.tf32.f32 %0, %1;" : "=r"(u) : "f"(v)); return u;
}
__device__ __forceinline__ void mma8(float* c, uint32_t a0, uint32_t a1,
                                     uint32_t a2, uint32_t a3,
                                     uint32_t b0, uint32_t b1) {
  asm volatile(
    "mma.sync.aligned.m16n8k8.row.col.f32.tf32.tf32.f32 "
    "{%0,%1,%2,%3},{%4,%5,%6,%7},{%8,%9},{%0,%1,%2,%3};\n"
    : "+f"(c[0]), "+f"(c[1]), "+f"(c[2]), "+f"(c[3])
    : "r"(a0), "r"(a1), "r"(a2), "r"(a3), "r"(b0), "r"(b1));
}
__device__ __forceinline__ void cpa16(uint32_t d, const void* s) {
  asm volatile("cp.async.cg.shared.global [%0], [%1], 16;" :: "r"(d), "l"(s));
}
__device__ __forceinline__ int kperm(int n) {        // pair (k, k+4) adjacent
  return (n & ~7) + ((n & 3) << 1) + ((n >> 2) & 1);
}

__global__ void k_init(const float* __restrict__ hidden) {
  int i = blockIdx.x * blockDim.x + threadIdx.x;   // 65536 threads
  if (i < B_ * N_) {
    int b = i >> 10, n = i & 1023;
    float v = __uint_as_float(f2tf(hidden[i]));
    g_hP[0][0][b * N_ + kperm(n)] = v;
    g_hP[0][1][b * N_ + kperm(n)] = v;
  }
  if (i < 2 * T_) g_bar[i] = 0;
}

// Pack U into fragment order (one uint4 per thread).
__global__ void __launch_bounds__(256) k_pack(PU pu) {
  unsigned i = blockIdx.x * 256 + threadIdx.x;
  unsigned lane = i & 31, g = (i >> 5) & 3, ks = (i >> 7) & 3,
           kq = (i >> 9) & 7, c = (i >> 12) & 3, tile = (i >> 14) & 63,
           dir = (i >> 20) & 1;
  int g4 = lane >> 2, tq = lane & 3;
  int row = tile * 16 + g4;
  int k = c * 256 + kq * 32 + ks * 8 + tq;
  const float* U = pu.U[dir * 4 + g];
  uint4 o;
  o.x = f2tf(U[(size_t)row * N_ + k]);
  o.y = f2tf(U[(size_t)(row + 8) * N_ + k]);
  o.z = f2tf(U[(size_t)row * N_ + k + 4]);
  o.w = f2tf(U[(size_t)(row + 8) * N_ + k + 4]);
  g_Upk[i] = o;
}

// ---------------- Phase 1: G[dg][t][n][b] = sum_m x[t_src,b,m] * W[m,n] ----
__device__ __forceinline__ float4 cvt4(float4 v) {
  float4 r;
  r.x = __uint_as_float(f2tf(v.x)); r.y = __uint_as_float(f2tf(v.y));
  r.z = __uint_as_float(f2tf(v.z)); r.w = __uint_as_float(f2tf(v.w));
  return r;
}

__global__ void __launch_bounds__(256) k_gemm_xw(const float* __restrict__ x, PW pw) {
  __shared__ __align__(16) float As[64][36];
  __shared__ __align__(16) float Bs[32][136];
  int tid = threadIdx.x;
  int wid = tid >> 5, lane = tid & 31;
  int g4 = lane >> 2, tq = lane & 3;
  int wm = wid & 1, wn = wid >> 1;
  int n0 = blockIdx.x * 128;
  int t = blockIdx.y;
  int dg = blockIdx.z;
  int dir = dg / 3;
  int t_src = dir ? (T_ - 1 - t) : t;
  const float* W = pw.p[dg];
  const float* xt = x + (size_t)t_src * (B_ * M_);

  float acc[2][4][4];
  #pragma unroll
  for (int a = 0; a < 2; a++)
    #pragma unroll
    for (int b = 0; b < 4; b++)
      #pragma unroll
      for (int cc = 0; cc < 4; cc++) acc[a][b][cc] = 0.f;

  for (int k0 = 0; k0 < M_; k0 += 32) {
    #pragma unroll
    for (int j = 0; j < 2; j++) {
      int i = tid + j * 256;
      int bb = i >> 3, kq = (i & 7) << 2;
      *(float4*)&As[bb][kq] = cvt4(*(const float4*)(xt + bb * M_ + k0 + kq));
    }
    #pragma unroll
    for (int j = 0; j < 4; j++) {
      int i = tid + j * 256;
      int kk = i >> 5, nq = (i & 31) << 2;
      *(float4*)&Bs[kk][nq] = cvt4(*(const float4*)(W + (size_t)(k0 + kk) * N_ + n0 + nq));
    }
    __syncthreads();
    #pragma unroll
    for (int ks = 0; ks < 32; ks += 8) {
      uint32_t af[2][4];
      #pragma unroll
      for (int mt = 0; mt < 2; mt++) {
        int r = wm * 32 + mt * 16 + g4;
        af[mt][0] = __float_as_uint(As[r][ks + tq]);
        af[mt][1] = __float_as_uint(As[r + 8][ks + tq]);
        af[mt][2] = __float_as_uint(As[r][ks + tq + 4]);
        af[mt][3] = __float_as_uint(As[r + 8][ks + tq + 4]);
      }
      #pragma unroll
      for (int nt = 0; nt < 4; nt++) {
        int ccol = wn * 32 + nt * 8 + g4;
        uint32_t b0 = __float_as_uint(Bs[ks + tq][ccol]);
        uint32_t b1 = __float_as_uint(Bs[ks + tq + 4][ccol]);
        #pragma unroll
        for (int mt = 0; mt < 2; mt++)
          mma8(acc[mt][nt], af[mt][0], af[mt][1], af[mt][2], af[mt][3], b0, b1);
      }
    }
    __syncthreads();
  }
  size_t gb = (size_t)(dg * T_ + t) * (N_ * B_);
  #pragma unroll
  for (int mt = 0; mt < 2; mt++) {
    int brow = wm * 32 + mt * 16 + g4;
    #pragma unroll
    for (int nt = 0; nt < 4; nt++) {
      int nc = n0 + wn * 32 + nt * 8 + 2 * tq;
      g_G[gb + (size_t)nc * B_ + brow]           = acc[mt][nt][0];
      g_G[gb + (size_t)(nc + 1) * B_ + brow]     = acc[mt][nt][1];
      g_G[gb + (size_t)nc * B_ + brow + 8]       = acc[mt][nt][2];
      g_G[gb + (size_t)(nc + 1) * B_ + brow + 8] = acc[mt][nt][3];
    }
  }
}

// ---------------- Phase 2: persistent recurrent kernel ---------------------
// 512 thr / block. Warp (rg,kq): rows rg*32..+32 (gates 2rg,2rg+1), 64 b-cols,
// k in [kq*32 + c*256, ...) per chunk. h staged via cp.async, dbl-buffered.
#define HS_STRIDE 264               // floats per b-row (256 used + pad)
#define HS_BUF    16896             // 64 * 264
#define ZS(q, r, cl) (((q) * 64 + (r)) * 66 + (cl))

__global__ void __launch_bounds__(512) k_recur(PU pu, float* __restrict__ out) {
  extern __shared__ float sm[];
  uint32_t smb = (uint32_t)__cvta_generic_to_shared(sm);
  int tid = threadIdx.x, wid = tid >> 5, lane = tid & 31;
  int g4 = lane >> 2, tq = lane & 3;
  int dir = blockIdx.x >> 6, tile = blockIdx.x & 63, rn = tile << 4;
  int rg = wid & 1, kq = wid >> 1;

  const uint4* upk_dt = g_Upk + (((size_t)dir * 64 + tile) << 14);

  // elementwise ownership: n = rn + n_e, batches b_e, b_e+1
  int n_e = tid >> 5;
  int b_e = (tid & 31) << 1;

  float bia[4];
  #pragma unroll
  for (int g = 0; g < 4; g++) bia[g] = pu.bia[dir * 4 + g][rn + n_e];
  const float* Gb0 = g_G + (size_t)(dir * 3 + 0) * T_ * N_ * B_;
  const float* Gb1 = g_G + (size_t)(dir * 3 + 1) * T_ * N_ * B_;
  const float* Gb2 = g_G + (size_t)(dir * 3 + 2) * T_ * N_ * B_;
  int hslot = kperm(rn + n_e);
  unsigned* barp = &g_bar[dir * T_];

  float creg[2] = {0.f, 0.f};

  for (int s = 0; s < T_; ++s) {
    const float* hsrc = g_hP[s & 1][dir];

    // prefetch this step's G values (consumed in epilogue)
    float gpre[2][3];
    #pragma unroll
    for (int e = 0; e < 2; e++) {
      size_t off = ((size_t)s * N_ + rn + n_e) * B_ + b_e + e;
      gpre[e][0] = __ldg(Gb0 + off);
      gpre[e][1] = __ldg(Gb1 + off);
      gpre[e][2] = __ldg(Gb2 + off);
    }

    float acc[2][8][4];
    #pragma unroll
    for (int m = 0; m < 2; m++)
      #pragma unroll
      for (int nt = 0; nt < 8; nt++)
        #pragma unroll
        for (int cc = 0; cc < 4; cc++) acc[m][nt][cc] = 0.f;

    // issue chunks 0 and 1
    #pragma unroll
    for (int c = 0; c < 2; c++) {
      #pragma unroll
      for (int j = 0; j < 8; j++) {
        int unit = tid + j * 512;
        int b = unit >> 6, s16 = unit & 63;
        cpa16(smb + (c * HS_BUF + b * HS_STRIDE + s16 * 4) * 4,
              hsrc + b * N_ + c * 256 + s16 * 4);
      }
      asm volatile("cp.async.commit_group;");
    }

    #pragma unroll
    for (int c = 0; c < 4; c++) {
      if (c < 3) asm volatile("cp.async.wait_group 1;");
      else       asm volatile("cp.async.wait_group 0;");
      __syncthreads();
      int buf = c & 1;
      const uint4* up = upk_dt + c * 4096 + kq * 512 + (2 * rg) * 32 + lane;
      const float* bb = sm + buf * HS_BUF + kq * 32 + 2 * tq;
      #pragma unroll
      for (int ks = 0; ks < 4; ++ks) {
        uint4 A0 = __ldg(&up[ks * 128]);
        uint4 A1 = __ldg(&up[ks * 128 + 32]);
        #pragma unroll
        for (int nt = 0; nt < 8; ++nt) {
          uint2 Bv = *(const uint2*)(bb + ks * 8 + (nt * 8 + g4) * HS_STRIDE);
          mma8(acc[0][nt], A0.x, A0.y, A0.z, A0.w, Bv.x, Bv.y);
          mma8(acc[1][nt], A1.x, A1.y, A1.z, A1.w, Bv.x, Bv.y);
        }
      }
      __syncthreads();
      if (c < 2) {            // issue chunk c+2 into buf c&1
        int cn = c + 2;
        #pragma unroll
        for (int j = 0; j < 8; j++) {
          int unit = tid + j * 512;
          int b = unit >> 6, s16 = unit & 63;
          cpa16(smb + (buf * HS_BUF + b * HS_STRIDE + s16 * 4) * 4,
                hsrc + b * N_ + cn * 256 + s16 * 4);
        }
        asm volatile("cp.async.commit_group;");
      }
    }

    // write k-partials (staging smem reused as zs[8][64][66])
    #pragma unroll
    for (int m = 0; m < 2; m++) {
      int gate = 2 * rg + m;
      #pragma unroll
      for (int nt = 0; nt < 8; nt++) {
        int cl = nt * 8 + 2 * tq;
        *(float2*)&sm[ZS(kq, gate * 16 + g4, cl)] =
            make_float2(acc[m][nt][0], acc[m][nt][1]);
        *(float2*)&sm[ZS(kq, gate * 16 + g4 + 8, cl)] =
            make_float2(acc[m][nt][2], acc[m][nt][3]);
      }
    }
    __syncthreads();

    // elementwise LSTM cell (2 elements per thread)
    float* hdst = g_hP[(s + 1) & 1][dir];
    int t_out = dir ? (T_ - 1 - s) : s;
    #pragma unroll
    for (int e = 0; e < 2; e++) {
      int b = b_e + e;
      float z0 = bia[0], z1 = bia[1], z2 = bia[2], z3 = bia[3];
      #pragma unroll
      for (int q = 0; q < 8; q++) {
        z0 += sm[ZS(q, 0 * 16 + n_e, b)];
        z1 += sm[ZS(q, 1 * 16 + n_e, b)];
        z2 += sm[ZS(q, 2 * 16 + n_e, b)];
        z3 += sm[ZS(q, 3 * 16 + n_e, b)];
      }
      float gf = gpre[e][0], gi = gpre[e][1], gc = gpre[e][2];
      float zf = z0 + gf, zi = z1 + gi, zc = z2 + gc, zo = z3 + gf; // o reuses gf
      float f  = 1.f / (1.f + __expf(-zf));
      float ig = 1.f / (1.f + __expf(-zi));
      float o  = 1.f / (1.f + __expf(-zo));
      float cn = f * creg[e] + ig * tanhf(zc);
      creg[e] = cn;
      float h = o * tanhf(cn);
      hdst[b * N_ + hslot] = __uint_as_float(f2tf(h));
      out[((size_t)t_out * B_ + b) * (2 * N_) + (size_t)dir * N_ + rn + n_e] = h;
    }

    // per-direction grid barrier (per-step counter, replay-safe)
    if (s < T_ - 1) {
      __threadfence();
      __syncthreads();
      if (tid == 0) {
        unsigned v = atomicAdd(&barp[s], 1) + 1;
        if (v < NBD) {
          while (*(volatile unsigned*)&barp[s] < NBD) { __nanosleep(32); }
        }
      }
      __syncthreads();
    }
  }
}

extern "C" void kernel_launch(void* const* d_in, const int* in_sizes, int n_in,
                              void* d_out, int out_size) {
  const float* x      = (const float*)d_in[0];
  const float* hidden = (const float*)d_in[1];
  PW pw;
  pw.p[0] = (const float*)d_in[2];   // Wf1
  pw.p[1] = (const float*)d_in[3];   // Wi1
  pw.p[2] = (const float*)d_in[4];   // Wc1
  pw.p[3] = (const float*)d_in[13];  // Wf2
  pw.p[4] = (const float*)d_in[14];  // Wi2
  pw.p[5] = (const float*)d_in[15];  // Wc2

  PU pu;  // gate order f,i,c,o
  pu.U[0] = (const float*)d_in[5];   // Uf1
  pu.U[1] = (const float*)d_in[6];   // Ui1
  pu.U[2] = (const float*)d_in[8];   // Uc1
  pu.U[3] = (const float*)d_in[7];   // Uo1
  pu.U[4] = (const float*)d_in[16];  // Uf2
  pu.U[5] = (const float*)d_in[17];  // Ui2
  pu.U[6] = (const float*)d_in[19];  // Uc2
  pu.U[7] = (const float*)d_in[18];  // Uo2
  pu.bia[0] = (const float*)d_in[9];   // bf1
  pu.bia[1] = (const float*)d_in[10];  // bi1
  pu.bia[2] = (const float*)d_in[12];  // bc1
  pu.bia[3] = (const float*)d_in[11];  // bo1
  pu.bia[4] = (const float*)d_in[20];  // bf2
  pu.bia[5] = (const float*)d_in[21];  // bi2
  pu.bia[6] = (const float*)d_in[23];  // bc2
  pu.bia[7] = (const float*)d_in[22];  // bo2

  static int smem_set = 0;
  if (!smem_set) {
    cudaFuncSetAttribute(k_recur, cudaFuncAttributeMaxDynamicSharedMemorySize,
                         2 * HS_BUF * (int)sizeof(float));
    smem_set = 1;
  }

  k_init<<<256, 256>>>(hidden);
  k_pack<<<8192, 256>>>(pu);
  k_gemm_xw<<<dim3(8, 256, 6), 256>>>(x, pw);
  k_recur<<<NB_REC, 512, 2 * HS_BUF * sizeof(float)>>>(pu, (float*)d_out);
}